// round 5
// baseline (speedup 1.0000x reference)
#include <cuda_runtime.h>
#include <cstdint>

#define GG 256
#define NN 512
#define KK 6
#define FF 64
#define TT (GG*NN)

typedef unsigned long long u64;

// scratch (static device arrays: no allocation allowed)
__device__ int   g_idx[TT*KK];
__device__ float g_hA[TT*FF];
__device__ float g_hB[TT*FF];
__device__ float g_part[(TT/128)*FF];   // per-128-row-block pooled partials

#define KNN_SMEM   ((NN*FF + NN) * 4 + 256)
#define LIN12_SMEM ((128*64 + 2*64*64 + 256) * 4)
#define GCONV_SMEM ((128*64 + 64*64 + 64) * 4)
#define LIN34_SMEM ((128*64 + 2*64*64 + 16*64 + 256) * 4)

// ---------------------------------------------------------------------------
// packed f32x2 helpers (issue-slot savings in the feature-layer GEMMs)
// ---------------------------------------------------------------------------
__device__ __forceinline__ u64 fma2(u64 a, u64 b, u64 c) {
    u64 d;
    asm("fma.rn.f32x2 %0, %1, %2, %3;" : "=l"(d) : "l"(a), "l"(b), "l"(c));
    return d;
}
__device__ __forceinline__ u64 pack2(float lo, float hi) {
    u64 d;
    asm("mov.b64 %0, {%1, %2};" : "=l"(d) : "f"(lo), "f"(hi));
    return d;
}
__device__ __forceinline__ float2 unpack2(u64 v) {
    float lo, hi;
    asm("mov.b64 {%0, %1}, %2;" : "=f"(lo), "=f"(hi) : "l"(v));
    return make_float2(lo, hi);
}

// ---------------------------------------------------------------------------
// tf32 mma.sync helpers (classic tensor path; sm_80+ PTX, no arch suffix)
// ---------------------------------------------------------------------------
__device__ __forceinline__ uint32_t f2tf32(float f) {
    uint32_t r;
    asm("cvt.rna.tf32.f32 %0, %1;" : "=r"(r) : "f"(f));
    return r;
}
__device__ __forceinline__ void mma_tf32(float d[4],
    uint32_t a0, uint32_t a1, uint32_t a2, uint32_t a3,
    uint32_t b0, uint32_t b1)
{
    asm volatile(
        "mma.sync.aligned.m16n8k8.row.col.f32.tf32.tf32.f32 "
        "{%0,%1,%2,%3}, {%4,%5,%6,%7}, {%8,%9}, {%0,%1,%2,%3};"
        : "+f"(d[0]), "+f"(d[1]), "+f"(d[2]), "+f"(d[3])
        : "r"(a0), "r"(a1), "r"(a2), "r"(a3), "r"(b0), "r"(b1));
}

// rotation swizzle: feature k of node n stored at k' = (k + 4*(n&15)) & 63
__device__ __forceinline__ int rotk(int n, int k) { return (k + 4 * (n & 15)) & 63; }

// ===========================================================================
// kNN via mma.sync tf32. One block per graph, 512 threads = 16 warps.
// Warp w owns 32 query rows [w*32, w*32+32). smem: fp32 graph (swizzled) + sq.
// Approx D = Xq.Xc^T (tf32), per-thread top-8 over disjoint 128-cand subset,
// shfl-merge 4 lanes -> 32 cands -> fp32-exact refine -> stable top-6.
// ===========================================================================
__global__ void __launch_bounds__(512, 1) knn_mma_kernel(const float* __restrict__ x)
{
    extern __shared__ float sm[];
    float* xs = sm;              // 512*64 swizzled fp32
    float* sq = sm + NN*FF;      // 512
    float4* xs4 = (float4*)xs;

    const int g    = blockIdx.x;
    const int tid  = threadIdx.x;
    const int warp = tid >> 5;
    const int lane = tid & 31;
    const int gID  = lane >> 2;   // group id 0..7
    const int tq   = lane & 3;    // thread-in-group 0..3
    const float* xg = x + (size_t)g * NN * FF;
    const float4* xg4 = (const float4*)xg;

    // fill swizzled smem copy
    for (int i = tid; i < NN * FF / 4; i += 512) {
        const int n  = i >> 4;
        const int i4 = i & 15;
        const int d4 = (i4 + (n & 15)) & 15;
        xs4[n * 16 + d4] = xg4[i];
    }
    // fp32 norms from global
    {
        const int r = tid;
        const float4* row = xg4 + r * 16;
        float s = 0.f;
        #pragma unroll
        for (int k2 = 0; k2 < 16; k2++) {
            float4 v = row[k2];
            s += v.x*v.x + v.y*v.y + v.z*v.z + v.w*v.w;
        }
        sq[r] = s;
    }
    __syncthreads();

    // query rows of this thread (4 rows: 2 row-tiles x {g, g+8})
    const int q0 = warp * 32;
    int qrow[4];
    qrow[0] = q0 + gID;       qrow[1] = q0 + 8 + gID;
    qrow[2] = q0 + 16 + gID;  qrow[3] = q0 + 24 + gID;

    // preload A fragments (tf32), 2 row-tiles x 8 k-steps x 4 regs
    uint32_t Af[2][8][4];
    #pragma unroll
    for (int kk = 0; kk < 8; kk++) {
        const int k0 = kk * 8;
        #pragma unroll
        for (int tile = 0; tile < 2; tile++) {
            const int ra = qrow[tile * 2];
            const int rb = qrow[tile * 2 + 1];
            Af[tile][kk][0] = f2tf32(xs[ra*64 + rotk(ra, k0 + tq)]);
            Af[tile][kk][1] = f2tf32(xs[rb*64 + rotk(rb, k0 + tq)]);
            Af[tile][kk][2] = f2tf32(xs[ra*64 + rotk(ra, k0 + tq + 4)]);
            Af[tile][kk][3] = f2tf32(xs[rb*64 + rotk(rb, k0 + tq + 4)]);
        }
    }

    // per-row approx top-8 trackers (key = sq[j] - 2*dot; sq[q] const per row)
    float sd[4][8]; int si[4][8];
    float wv[4]; int ws[4];
    #pragma unroll
    for (int r = 0; r < 4; r++) {
        #pragma unroll
        for (int s = 0; s < 8; s++) { sd[r][s] = 3.0e38f; si[r][s] = 0; }
        wv[r] = 3.0e38f; ws[r] = 0;
    }

    #pragma unroll 1
    for (int ct = 0; ct < 64; ct++) {
        const int cand0 = ct * 8;
        const int nb = cand0 + gID;            // B-fragment node for this thread
        float acc0[4] = {0.f, 0.f, 0.f, 0.f};
        float acc1[4] = {0.f, 0.f, 0.f, 0.f};
        #pragma unroll
        for (int kk = 0; kk < 8; kk++) {
            const int k0 = kk * 8;
            const uint32_t b0 = f2tf32(xs[nb*64 + rotk(nb, k0 + tq)]);
            const uint32_t b1 = f2tf32(xs[nb*64 + rotk(nb, k0 + tq + 4)]);
            mma_tf32(acc0, Af[0][kk][0], Af[0][kk][1], Af[0][kk][2], Af[0][kk][3], b0, b1);
            mma_tf32(acc1, Af[1][kk][0], Af[1][kk][1], Af[1][kk][2], Af[1][kk][3], b0, b1);
        }
        // this thread's D elements: rows qrow[0..3], cols c0 = cand0+2*tq, c0+1
        const int c0 = cand0 + 2 * tq;
        const int c1 = c0 + 1;
        const float sq_c0 = sq[c0], sq_c1 = sq[c1];
        const float key[4][2] = {
            { sq_c0 - 2.f*acc0[0], sq_c1 - 2.f*acc0[1] },
            { sq_c0 - 2.f*acc0[2], sq_c1 - 2.f*acc0[3] },
            { sq_c0 - 2.f*acc1[0], sq_c1 - 2.f*acc1[1] },
            { sq_c0 - 2.f*acc1[2], sq_c1 - 2.f*acc1[3] } };
        #pragma unroll
        for (int r = 0; r < 4; r++) {
            #pragma unroll
            for (int cc = 0; cc < 2; cc++) {
                const int j = cc ? c1 : c0;
                const float d = key[r][cc];
                if (j != qrow[r] && d < wv[r]) {
                    sd[r][ws[r]] = d; si[r][ws[r]] = j;
                    wv[r] = sd[r][0]; ws[r] = 0;
                    #pragma unroll
                    for (int s = 1; s < 8; s++)
                        if (sd[r][s] > wv[r]) { wv[r] = sd[r][s]; ws[r] = s; }
                }
            }
        }
    }

    // merge across the 4 lanes of each group (disjoint candidate subsets),
    // then fp32-exact refine on lane tq==0
    const int base = g * NN;
    #pragma unroll 1
    for (int r = 0; r < 4; r++) {
        float bd[8]; int bi[8];
        float w8 = 3.0e38f; int w8s = 0;
        #pragma unroll
        for (int s = 0; s < 8; s++) { bd[s] = 3.0e38f; bi[s] = 0; }

        #pragma unroll
        for (int st = 0; st < 4; st++) {
            #pragma unroll
            for (int s = 0; s < 8; s++) {
                const float d = __shfl_sync(0xffffffffu, sd[r][s], (gID << 2) + st);
                const int   i = __shfl_sync(0xffffffffu, si[r][s], (gID << 2) + st);
                if (tq == 0 && d < w8) {
                    bd[w8s] = d; bi[w8s] = i;
                    w8 = bd[0]; w8s = 0;
                    #pragma unroll
                    for (int s2 = 1; s2 < 8; s2++)
                        if (bd[s2] > w8) { w8 = bd[s2]; w8s = s2; }
                }
            }
        }

        if (tq == 0) {
            // sort 8 candidate indices ascending (stable tie-break)
            #pragma unroll
            for (int a = 0; a < 7; a++)
                #pragma unroll
                for (int b = a + 1; b < 8; b++)
                    if (bi[b] < bi[a]) { int t = bi[a]; bi[a] = bi[b]; bi[b] = t; }

            const int q = qrow[r];
            const float sqq = sq[q];
            // preload query row in logical order from swizzled smem
            float4 qv[16];
            #pragma unroll
            for (int i4 = 0; i4 < 16; i4++)
                qv[i4] = xs4[q * 16 + ((i4 + (q & 15)) & 15)];

            float bd6[6]; int bi6[6];
            float w6 = 3.0e38f; int w6s = 0;
            #pragma unroll
            for (int s = 0; s < 6; s++) { bd6[s] = 3.0e38f; bi6[s] = 0; }

            #pragma unroll
            for (int s = 0; s < 8; s++) {
                const int c = bi[s];
                float a0 = 0.f, a1 = 0.f;
                #pragma unroll
                for (int i4 = 0; i4 < 16; i4 += 2) {
                    const float4 v0 = xs4[c * 16 + ((i4     + (c & 15)) & 15)];
                    const float4 v1 = xs4[c * 16 + ((i4 + 1 + (c & 15)) & 15)];
                    a0 = fmaf(qv[i4].x,   v0.x, a0); a0 = fmaf(qv[i4].y,   v0.y, a0);
                    a0 = fmaf(qv[i4].z,   v0.z, a0); a0 = fmaf(qv[i4].w,   v0.w, a0);
                    a1 = fmaf(qv[i4+1].x, v1.x, a1); a1 = fmaf(qv[i4+1].y, v1.y, a1);
                    a1 = fmaf(qv[i4+1].z, v1.z, a1); a1 = fmaf(qv[i4+1].w, v1.w, a1);
                }
                const float dot = a0 + a1;
                const float d = __fsub_rn(sqq + sq[c], __fmul_rn(2.f, dot));
                if (d < w6) {
                    bd6[w6s] = d; bi6[w6s] = c;
                    w6 = bd6[0]; w6s = 0;
                    #pragma unroll
                    for (int u = 1; u < 6; u++)
                        if (bd6[u] > w6) { w6 = bd6[u]; w6s = u; }
                }
            }
            #pragma unroll
            for (int s = 0; s < 6; s++)
                g_idx[(size_t)(base + q) * KK + s] = base + bi6[s];
        }
    }
}

// ---------------------------------------------------------------------------
// 128-row x 64-col tile matmul from smem, FFMA2 over column pairs.
// ---------------------------------------------------------------------------
__device__ __forceinline__ void mm_tile2(const float* __restrict__ xs,
                                         const float* __restrict__ Ws,
                                         u64 acc2[8][2], int rg, int cg)
{
    #pragma unroll
    for (int r = 0; r < 8; r++) { acc2[r][0] = 0ull; acc2[r][1] = 0ull; }
    #pragma unroll 2
    for (int k = 0; k < 64; k += 4) {
        const ulonglong2 w0 = *(const ulonglong2*)&Ws[(k+0)*64 + cg];
        const ulonglong2 w1 = *(const ulonglong2*)&Ws[(k+1)*64 + cg];
        const ulonglong2 w2 = *(const ulonglong2*)&Ws[(k+2)*64 + cg];
        const ulonglong2 w3 = *(const ulonglong2*)&Ws[(k+3)*64 + cg];
        #pragma unroll
        for (int r = 0; r < 8; r++) {
            const float4 xv = *(const float4*)&xs[(rg*8 + r)*64 + k];
            const u64 x0 = pack2(xv.x, xv.x);
            const u64 x1 = pack2(xv.y, xv.y);
            const u64 x2 = pack2(xv.z, xv.z);
            const u64 x3 = pack2(xv.w, xv.w);
            acc2[r][0] = fma2(x0, w0.x, acc2[r][0]);
            acc2[r][1] = fma2(x0, w0.y, acc2[r][1]);
            acc2[r][0] = fma2(x1, w1.x, acc2[r][0]);
            acc2[r][1] = fma2(x1, w1.y, acc2[r][1]);
            acc2[r][0] = fma2(x2, w2.x, acc2[r][0]);
            acc2[r][1] = fma2(x2, w2.y, acc2[r][1]);
            acc2[r][0] = fma2(x3, w3.x, acc2[r][0]);
            acc2[r][1] = fma2(x3, w3.y, acc2[r][1]);
        }
    }
}

// ---------------------------------------------------------------------------
// Fused prelu(x@W1+b1) -> prelu(.@W2+b2). 1024 blocks x 256 thr, 128 rows/block.
// ---------------------------------------------------------------------------
__global__ void __launch_bounds__(256) lin12_kernel(
    const float* __restrict__ x,
    const float* __restrict__ W1, const float* __restrict__ b1, const float* __restrict__ a1,
    const float* __restrict__ W2, const float* __restrict__ b2, const float* __restrict__ a2,
    float* __restrict__ out)
{
    extern __shared__ float smf[];
    float* xs = smf;             // 8192
    float* Ws = smf + 8192;      // 8192 (W1 | W2)
    float* bs = smf + 16384;     // 256 (b1,a1,b2,a2)
    const int tid = threadIdx.x;
    const size_t rowbase = (size_t)blockIdx.x * 128;

    float4* xs4 = (float4*)xs;
    const float4* xin = (const float4*)(x + rowbase * FF);
    for (int i = tid; i < 2048; i += 256) xs4[i] = xin[i];
    float4* Ws4 = (float4*)Ws;
    for (int i = tid; i < 1024; i += 256) {
        Ws4[i]        = ((const float4*)W1)[i];
        Ws4[1024 + i] = ((const float4*)W2)[i];
    }
    if (tid < 64) { bs[tid] = b1[tid]; bs[64+tid] = a1[tid]; bs[128+tid] = b2[tid]; bs[192+tid] = a2[tid]; }
    __syncthreads();

    const int rg = tid >> 4, cg = (tid & 15) * 4;
    u64 acc2[8][2];
    mm_tile2(xs, Ws, acc2, rg, cg);
    __syncthreads();
    #pragma unroll
    for (int r = 0; r < 8; r++) {
        const float2 p0 = unpack2(acc2[r][0]);
        const float2 p1 = unpack2(acc2[r][1]);
        const float a4[4] = {p0.x, p0.y, p1.x, p1.y};
        #pragma unroll
        for (int c = 0; c < 4; c++) {
            float v = a4[c] + bs[cg + c];
            v = (v >= 0.f) ? v : v * bs[64 + cg + c];
            xs[(rg*8 + r)*64 + cg + c] = v;
        }
    }
    __syncthreads();
    mm_tile2(xs, Ws + 4096, acc2, rg, cg);
    #pragma unroll
    for (int r = 0; r < 8; r++) {
        const float2 p0 = unpack2(acc2[r][0]);
        const float2 p1 = unpack2(acc2[r][1]);
        float4 o;
        float v;
        v = p0.x + bs[128+cg+0]; o.x = (v >= 0.f) ? v : v * bs[192+cg+0];
        v = p0.y + bs[128+cg+1]; o.y = (v >= 0.f) ? v : v * bs[192+cg+1];
        v = p1.x + bs[128+cg+2]; o.z = (v >= 0.f) ? v : v * bs[192+cg+2];
        v = p1.y + bs[128+cg+3]; o.w = (v >= 0.f) ? v : v * bs[192+cg+3];
        *(float4*)&out[(rowbase + rg*8 + r)*FF + cg] = o;
    }
}

// ---------------------------------------------------------------------------
// GeneralConv: out[i] = (sum_{j in nbr(i)} h[j]) @ W + 6*b + h[i]
// ---------------------------------------------------------------------------
__global__ void __launch_bounds__(256) gconv_kernel(
    const float* __restrict__ hin,
    const float* __restrict__ Wc, const float* __restrict__ bc,
    float* __restrict__ out)
{
    extern __shared__ float smf[];
    float* ss = smf;             // 8192 (gathered neighbor sums)
    float* Ws = smf + 8192;      // 4096
    float* bs = smf + 12288;     // 64
    const int tid = threadIdx.x;
    const size_t rowbase = (size_t)blockIdx.x * 128;

    float4* Ws4 = (float4*)Ws;
    for (int i = tid; i < 1024; i += 256) Ws4[i] = ((const float4*)Wc)[i];
    if (tid < 64) bs[tid] = bc[tid];

    {   // gather-sum: 2 threads per row (32 feats each)
        const int r = tid >> 1;
        const int half = (tid & 1) * 8;     // float4 chunk offset
        const int* ip = g_idx + ((size_t)rowbase + r) * KK;
        float4 acc4[8];
        #pragma unroll
        for (int c = 0; c < 8; c++) acc4[c] = make_float4(0.f, 0.f, 0.f, 0.f);
        #pragma unroll
        for (int j = 0; j < KK; j++) {
            const float4* nb = (const float4*)(hin + (size_t)ip[j] * FF) + half;
            #pragma unroll
            for (int c = 0; c < 8; c++) {
                float4 v = nb[c];
                acc4[c].x += v.x; acc4[c].y += v.y; acc4[c].z += v.z; acc4[c].w += v.w;
            }
        }
        float4* ss4 = (float4*)ss;
        #pragma unroll
        for (int c = 0; c < 8; c++) ss4[r*16 + half + c] = acc4[c];
    }
    __syncthreads();

    const int rg = tid >> 4, cg = (tid & 15) * 4;
    u64 acc2[8][2];
    mm_tile2(ss, Ws, acc2, rg, cg);
    #pragma unroll
    for (int r = 0; r < 8; r++) {
        const size_t row = rowbase + rg*8 + r;
        const float4 hv = *(const float4*)&hin[row*FF + cg];
        const float2 p0 = unpack2(acc2[r][0]);
        const float2 p1 = unpack2(acc2[r][1]);
        float4 o;
        o.x = p0.x + 6.f*bs[cg+0] + hv.x;
        o.y = p0.y + 6.f*bs[cg+1] + hv.y;
        o.z = p1.x + 6.f*bs[cg+2] + hv.z;
        o.w = p1.y + 6.f*bs[cg+3] + hv.w;
        *(float4*)&out[row*FF + cg] = o;
    }
}

// ---------------------------------------------------------------------------
// Fused prelu(.@W3+b3) -> prelu(.@W4+b4) -> per-block column partial sums (pool)
// ---------------------------------------------------------------------------
__global__ void __launch_bounds__(256) lin34_pool_kernel(
    const float* __restrict__ hin,
    const float* __restrict__ W3, const float* __restrict__ b3, const float* __restrict__ a3,
    const float* __restrict__ W4, const float* __restrict__ b4, const float* __restrict__ a4)
{
    extern __shared__ float smf[];
    float* xs = smf;             // 8192
    float* Ws = smf + 8192;      // 8192
    float* ps = smf + 16384;     // 1024
    float* bs = smf + 17408;     // 256
    const int tid = threadIdx.x;
    const size_t rowbase = (size_t)blockIdx.x * 128;

    float4* xs4 = (float4*)xs;
    const float4* xin = (const float4*)(hin + rowbase * FF);
    for (int i = tid; i < 2048; i += 256) xs4[i] = xin[i];
    float4* Ws4 = (float4*)Ws;
    for (int i = tid; i < 1024; i += 256) {
        Ws4[i]        = ((const float4*)W3)[i];
        Ws4[1024 + i] = ((const float4*)W4)[i];
    }
    if (tid < 64) { bs[tid] = b3[tid]; bs[64+tid] = a3[tid]; bs[128+tid] = b4[tid]; bs[192+tid] = a4[tid]; }
    __syncthreads();

    const int rg = tid >> 4, cg = (tid & 15) * 4;
    u64 acc2[8][2];
    mm_tile2(xs, Ws, acc2, rg, cg);
    __syncthreads();
    #pragma unroll
    for (int r = 0; r < 8; r++) {
        const float2 p0 = unpack2(acc2[r][0]);
        const float2 p1 = unpack2(acc2[r][1]);
        const float a4[4] = {p0.x, p0.y, p1.x, p1.y};
        #pragma unroll
        for (int c = 0; c < 4; c++) {
            float v = a4[c] + bs[cg + c];
            v = (v >= 0.f) ? v : v * bs[64 + cg + c];
            xs[(rg*8 + r)*64 + cg + c] = v;
        }
    }
    __syncthreads();
    mm_tile2(xs, Ws + 4096, acc2, rg, cg);

    float cs[4] = {0.f, 0.f, 0.f, 0.f};
    #pragma unroll
    for (int r = 0; r < 8; r++) {
        const float2 p0 = unpack2(acc2[r][0]);
        const float2 p1 = unpack2(acc2[r][1]);
        const float a4[4] = {p0.x, p0.y, p1.x, p1.y};
        #pragma unroll
        for (int c = 0; c < 4; c++) {
            float v = a4[c] + bs[128 + cg + c];
            v = (v >= 0.f) ? v : v * bs[192 + cg + c];
            cs[c] += v;
        }
    }
    #pragma unroll
    for (int c = 0; c < 4; c++) ps[rg*64 + cg + c] = cs[c];
    __syncthreads();

    if (tid < 64) {
        float s = 0.f;
        #pragma unroll
        for (int i = 0; i < 16; i++) s += ps[i*64 + tid];
        g_part[(size_t)blockIdx.x * FF + tid] = s;
    }
}

// ---------------------------------------------------------------------------
// Head MLP: pooled[64] -> 256 -> 256 -> 64 -> 1 (leaky 0.2). One block per graph.
// ---------------------------------------------------------------------------
__global__ void __launch_bounds__(256) head_kernel(
    const float* __restrict__ Wh1, const float* __restrict__ bh1,
    const float* __restrict__ Wh2, const float* __restrict__ bh2,
    const float* __restrict__ Wh3, const float* __restrict__ bh3,
    const float* __restrict__ Wh4, const float* __restrict__ bh4,
    float* __restrict__ out)
{
    __shared__ float p[64], y1[256], y2[256], y3[64];
    const int g = blockIdx.x, t = threadIdx.x;
    if (t < 64) {
        p[t] = g_part[(size_t)(g*4 + 0)*FF + t] + g_part[(size_t)(g*4 + 1)*FF + t]
             + g_part[(size_t)(g*4 + 2)*FF + t] + g_part[(size_t)(g*4 + 3)*FF + t];
    }
    __syncthreads();
    {
        float v = bh1[t];
        #pragma unroll 4
        for (int k = 0; k < 64; k++) v = fmaf(p[k], Wh1[k*256 + t], v);
        y1[t] = (v >= 0.f) ? v : 0.2f * v;
    }
    __syncthreads();
    {
        float v = bh2[t];
        #pragma unroll 4
        for (int k = 0; k < 256; k++) v = fmaf(y1[k], Wh2[k*256 + t], v);
        y2[t] = (v >= 0.f) ? v : 0.2f * v;
    }
    __syncthreads();
    if (t < 64) {
        float v = bh3[t];
        #pragma unroll 4
        for (int k = 0; k < 256; k++) v = fmaf(y2[k], Wh3[k*64 + t], v);
        y3[t] = (v >= 0.f) ? v : 0.2f * v;
    }
    __syncthreads();
    if (t == 0) {
        float v = bh4[0];
        #pragma unroll
        for (int k = 0; k < 64; k++) v = fmaf(y3[k], Wh4[k], v);
        out[g] = v;
    }
}

// ---------------------------------------------------------------------------
extern "C" void kernel_launch(void* const* d_in, const int* in_sizes, int n_in,
                              void* d_out, int out_size)
{
    const float* x   = (const float*)d_in[0];
    const float* W1  = (const float*)d_in[1];
    const float* b1  = (const float*)d_in[2];
    const float* a1  = (const float*)d_in[3];
    const float* W2  = (const float*)d_in[4];
    const float* b2  = (const float*)d_in[5];
    const float* a2  = (const float*)d_in[6];
    const float* Wc1 = (const float*)d_in[7];
    const float* bc1 = (const float*)d_in[8];
    const float* Wc2 = (const float*)d_in[9];
    const float* bc2 = (const float*)d_in[10];
    const float* Wc3 = (const float*)d_in[11];
    const float* bc3 = (const float*)d_in[12];
    const float* Wc4 = (const float*)d_in[13];
    const float* bc4 = (const float*)d_in[14];
    const float* W3  = (const float*)d_in[15];
    const float* b3  = (const float*)d_in[16];
    const float* a3  = (const float*)d_in[17];
    const float* W4  = (const float*)d_in[18];
    const float* b4  = (const float*)d_in[19];
    const float* a4  = (const float*)d_in[20];
    const float* Wh1 = (const float*)d_in[21];
    const float* bh1 = (const float*)d_in[22];
    const float* Wh2 = (const float*)d_in[23];
    const float* bh2 = (const float*)d_in[24];
    const float* Wh3 = (const float*)d_in[25];
    const float* bh3 = (const float*)d_in[26];
    const float* Wh4 = (const float*)d_in[27];
    const float* bh4 = (const float*)d_in[28];
    float* out = (float*)d_out;

    float *hA = nullptr, *hB = nullptr;
    cudaGetSymbolAddress((void**)&hA, g_hA);
    cudaGetSymbolAddress((void**)&hB, g_hB);

    cudaFuncSetAttribute(knn_mma_kernel,   cudaFuncAttributeMaxDynamicSharedMemorySize, KNN_SMEM);
    cudaFuncSetAttribute(lin12_kernel,     cudaFuncAttributeMaxDynamicSharedMemorySize, LIN12_SMEM);
    cudaFuncSetAttribute(gconv_kernel,     cudaFuncAttributeMaxDynamicSharedMemorySize, GCONV_SMEM);
    cudaFuncSetAttribute(lin34_pool_kernel,cudaFuncAttributeMaxDynamicSharedMemorySize, LIN34_SMEM);

    knn_mma_kernel<<<GG, 512, KNN_SMEM>>>(x);
    lin12_kernel<<<TT/128, 256, LIN12_SMEM>>>(x, W1, b1, a1, W2, b2, a2, hA);
    gconv_kernel<<<TT/128, 256, GCONV_SMEM>>>(hA, Wc1, bc1, hB);
    gconv_kernel<<<TT/128, 256, GCONV_SMEM>>>(hB, Wc2, bc2, hA);
    gconv_kernel<<<TT/128, 256, GCONV_SMEM>>>(hA, Wc3, bc3, hB);
    gconv_kernel<<<TT/128, 256, GCONV_SMEM>>>(hB, Wc4, bc4, hA);
    lin34_pool_kernel<<<TT/128, 256, LIN34_SMEM>>>(hA, W3, b3, a3, W4, b4, a4);
    head_kernel<<<GG, 256>>>(Wh1, bh1, Wh2, bh2, Wh3, bh3, Wh4, bh4, out);
}